// round 5
// baseline (speedup 1.0000x reference)
#include <cuda_runtime.h>
#include <stdint.h>

#define B 16
#define N 4096
#define F 128
#define K 1024
#define ROWS_PER_CTA 16
#define HB 11
#define NB (1 << HB)   // 2048 histogram buckets

typedef unsigned long long u64;
typedef unsigned int u32;

// scratch (no allocations allowed)
__device__ float g_scores[B * N];
__device__ int   g_hist[B * NB];
__device__ int   g_topk_idx[B * K];
__device__ float g_topk_val[B * K];
__device__ int   g_scol[B * K];   // selected columns sorted ascending
__device__ int   g_spos[B * K];   // original top-k position of that column

__device__ __forceinline__ unsigned map_f32(float f) {
    unsigned u = __float_as_uint(f);
    return (u & 0x80000000u) ? ~u : (u | 0x80000000u);
}

// ---------------------------------------------------------------------------
// Kernel 0: zero the per-batch histograms (graph replays need fresh zeros)
// ---------------------------------------------------------------------------
__global__ void zero_hist_kernel() {
    int i = blockIdx.x * blockDim.x + threadIdx.x;
    if (i < B * NB) g_hist[i] = 0;
}

// ---------------------------------------------------------------------------
// Kernel 1: scores[b,n] = dot(node_embed[b,n,:], weight_p)  (one warp per row)
// also accumulates the per-batch score histogram with chip-wide REDG.
// ---------------------------------------------------------------------------
__global__ void scores_kernel(const float* __restrict__ ne,
                              const float* __restrict__ w) {
    int warp = (blockIdx.x * blockDim.x + threadIdx.x) >> 5;
    int lane = threadIdx.x & 31;
    if (warp >= B * N) return;
    const float4* nrow = reinterpret_cast<const float4*>(ne + (size_t)warp * F);
    const float4* wv   = reinterpret_cast<const float4*>(w);
    float4 a  = nrow[lane];
    float4 b4 = wv[lane];
    float s = a.x * b4.x + a.y * b4.y + a.z * b4.z + a.w * b4.w;
#pragma unroll
    for (int off = 16; off; off >>= 1)
        s += __shfl_xor_sync(0xffffffffu, s, off);
    if (lane == 0) {
        g_scores[warp] = s;
        int b = warp >> 12;                       // row / N
        atomicAdd(&g_hist[b * NB + (map_f32(s) >> (32 - HB))], 1);
    }
}

// ---------------------------------------------------------------------------
// Kernel 2: radix cutoff (precomputed hist) + hybrid register/smem bitonic.
// key = (monotonic(score) << 12) | (4095 - idx) -> desc sort == jax top_k order
// ---------------------------------------------------------------------------
__device__ __forceinline__ u64 u64max(u64 a, u64 b) { return a > b ? a : b; }
__device__ __forceinline__ u64 u64min(u64 a, u64 b) { return a < b ? a : b; }

__device__ __forceinline__ void reg_stages(u64& e0, u64& e1, int i0, int i1,
                                           int lane, int kk) {
    if (kk >= 64) {
        bool desc = ((i0 & kk) == 0);
        if (desc ? (e0 < e1) : (e0 > e1)) { u64 t = e0; e0 = e1; e1 = t; }
    }
#pragma unroll
    for (int j = 16; j >= 1; j >>= 1) {
        if (j <= (kk >> 1)) {
            bool d0 = ((i0 & kk) == 0);
            bool d1 = ((i1 & kk) == 0);
            bool up = (lane & j) != 0;
            u64 p0 = __shfl_xor_sync(0xffffffffu, e0, j);
            u64 p1 = __shfl_xor_sync(0xffffffffu, e1, j);
            e0 = (d0 ^ up) ? u64max(e0, p0) : u64min(e0, p0);
            e1 = (d1 ^ up) ? u64max(e1, p1) : u64min(e1, p1);
        }
    }
}

__global__ void __launch_bounds__(1024) topk_kernel() {
    __shared__ u64 cand[4096];       // 32 KB
    __shared__ int hist[NB];         //  8 KB (reused as bitmap later)
    __shared__ int wsum[32];
    __shared__ int s_t0, s_cnt;

    const int b    = blockIdx.x;
    const int tid  = threadIdx.x;
    const int lane = tid & 31;
    const int warp = tid >> 5;
    const float* sc = g_scores + b * N;

    hist[tid]        = g_hist[b * NB + tid];
    hist[tid + 1024] = g_hist[b * NB + tid + 1024];

    u64 kreg[4];
#pragma unroll
    for (int q = 0; q < 4; q++) {
        int i = tid + q * 1024;
        unsigned m = map_f32(sc[i]);
        kreg[q] = (((u64)m) << 12) | (unsigned)(N - 1 - i);
    }
    __syncthreads();

    // ---- cutoff bucket t0 = max t such that count(bucket >= t) >= K ----
    {
        int p = hist[2 * tid] + hist[2 * tid + 1];
        int ws = p;
#pragma unroll
        for (int off = 16; off; off >>= 1)
            ws += __shfl_xor_sync(0xffffffffu, ws, off);
        if (lane == 0) wsum[warp] = ws;
    }
    __syncthreads();
    if (warp == 0) {
        int v = wsum[lane];
        int s = v;
#pragma unroll
        for (int off = 1; off < 32; off <<= 1) {
            int t = __shfl_down_sync(0xffffffffu, s, off);
            if (lane + off < 32) s += t;
        }
        unsigned mm = __ballot_sync(0xffffffffu, s >= K);
        int wstar = 31 - __clz(mm);
        int sW = __shfl_sync(0xffffffffu, s, wstar);
        int vW = __shfl_sync(0xffffffffu, v, wstar);
        int run = sW - vW;
        int segbase = wstar * 64;
        int t0 = 0;
#pragma unroll
        for (int c = 1; c >= 0; c--) {
            int bkt = segbase + c * 32 + lane;
            int hv = hist[bkt];
            int s2 = hv;
#pragma unroll
            for (int off = 1; off < 32; off <<= 1) {
                int t = __shfl_down_sync(0xffffffffu, s2, off);
                if (lane + off < 32) s2 += t;
            }
            unsigned m2 = __ballot_sync(0xffffffffu, run + s2 >= K);
            if (m2) { t0 = segbase + c * 32 + (31 - __clz(m2)); break; }
            run += __shfl_sync(0xffffffffu, s2, 0);
        }
        if (lane == 0) { s_t0 = t0; s_cnt = 0; }
    }
    __syncthreads();

    // ---- compact candidates (bucket >= t0), warp-aggregated atomics ----
    int t0 = s_t0;
#pragma unroll
    for (int q = 0; q < 4; q++) {
        bool p = (int)(kreg[q] >> 33) >= t0;
        unsigned mask = __ballot_sync(0xffffffffu, p);
        int cnt = __popc(mask);
        int base = 0;
        if (lane == 0 && cnt) base = atomicAdd(&s_cnt, cnt);
        base = __shfl_sync(0xffffffffu, base, 0);
        if (p) cand[base + __popc(mask & ((1u << lane) - 1u))] = kreg[q];
    }
    __syncthreads();
    int M = s_cnt;

    if (M <= 2048) {
        for (int i = M + tid; i < 2048; i += 1024) cand[i] = 0;
        __syncthreads();

        const int base = warp * 64;
        const int i0 = base + lane, i1 = base + 32 + lane;
        u64 e0, e1;

        e0 = cand[i0]; e1 = cand[i1];
#pragma unroll
        for (int kk = 2; kk <= 64; kk <<= 1)
            reg_stages(e0, e1, i0, i1, lane, kk);
        cand[i0] = e0; cand[i1] = e1;
        __syncthreads();

#pragma unroll
        for (int kk = 128; kk <= 2048; kk <<= 1) {
            for (int j = kk >> 1; j >= 64; j >>= 1) {
                int i = 2 * tid - (tid & (j - 1));
                int x = i + j;
                bool desc = ((i & kk) == 0);
                u64 a = cand[i], c = cand[x];
                if (desc ? (a < c) : (a > c)) { cand[i] = c; cand[x] = a; }
                __syncthreads();
            }
            e0 = cand[i0]; e1 = cand[i1];
            reg_stages(e0, e1, i0, i1, lane, kk);
            cand[i0] = e0; cand[i1] = e1;
            __syncthreads();
        }
    } else {
        // safety fallback: plain full bitonic over all 4096 keys
#pragma unroll
        for (int q = 0; q < 4; q++) cand[tid + q * 1024] = kreg[q];
        __syncthreads();
        for (int kk = 2; kk <= 4096; kk <<= 1) {
            for (int j = kk >> 1; j > 0; j >>= 1) {
                for (int q = tid; q < 2048; q += 1024) {
                    int i = 2 * q - (q & (j - 1));
                    int x = i + j;
                    bool desc = ((i & kk) == 0);
                    u64 a = cand[i], c = cand[x];
                    if (desc ? (a < c) : (a > c)) { cand[i] = c; cand[x] = a; }
                }
                __syncthreads();
            }
        }
    }

    // ---- emit top-K (sorted desc) ----
    u64 key = cand[tid];
    int idx = (N - 1) - (int)(key & 0xFFFu);
    unsigned m = (unsigned)(key >> 12);
    unsigned u = (m & 0x80000000u) ? (m ^ 0x80000000u) : ~m;
    g_topk_idx[b * K + tid] = idx;
    g_topk_val[b * K + tid] = __uint_as_float(u);

    // ---- column-ascending permutation via bitmap counting-rank ----
    u32* bits = (u32*)hist;           // 4096-bit presence bitmap
    int* wordpref = hist + 128;
    if (tid < 128) bits[tid] = 0;
    __syncthreads();
    atomicOr(&bits[idx >> 5], 1u << (idx & 31));
    __syncthreads();
    if (warp == 0) {
        int s0 = __popc(bits[4 * lane]);
        int s1 = __popc(bits[4 * lane + 1]);
        int s2 = __popc(bits[4 * lane + 2]);
        int s3 = __popc(bits[4 * lane + 3]);
        int tot = s0 + s1 + s2 + s3;
        int ex = tot;
#pragma unroll
        for (int off = 1; off < 32; off <<= 1) {
            int t = __shfl_up_sync(0xffffffffu, ex, off);
            if (lane >= off) ex += t;
        }
        ex -= tot;
        wordpref[4 * lane]     = ex;
        wordpref[4 * lane + 1] = ex + s0;
        wordpref[4 * lane + 2] = ex + s0 + s1;
        wordpref[4 * lane + 3] = ex + s0 + s1 + s2;
    }
    __syncthreads();
    int wrd = idx >> 5, bit = idx & 31;
    int rank = wordpref[wrd] + __popc(bits[wrd] & ((1u << bit) - 1u));
    g_scol[b * K + rank] = idx;
    g_spos[b * K + rank] = tid;
}

// ---------------------------------------------------------------------------
// Kernel 3: pooled_nodes[b,r,:] = node_embed[b, idx, :] * tanh(val)
// ---------------------------------------------------------------------------
__global__ void nodes_kernel(const float* __restrict__ ne,
                             float* __restrict__ out) {
    int warp = (blockIdx.x * blockDim.x + threadIdx.x) >> 5;
    int lane = threadIdx.x & 31;
    if (warp >= B * K) return;
    int b   = warp >> 10;
    int idx = g_topk_idx[warp];
    float g = tanhf(g_topk_val[warp]);
    const float4* src = reinterpret_cast<const float4*>(
        ne + ((size_t)b * N + idx) * F);
    float4* dst = reinterpret_cast<float4*>(out + (size_t)warp * F);
    float4 v = src[lane];
    v.x *= g; v.y *= g; v.z *= g; v.w *= g;
    dst[lane] = v;
}

// ---------------------------------------------------------------------------
// Kernel 4: pooled_adj[b,i,j] = adj[b, row_i, col_j]
// Sorted-column gather, pipelined rows, double-buffered smem order-restore,
// coalesced float4 stores. 16 rows/CTA -> single wave on 148 SMs.
// ---------------------------------------------------------------------------
__global__ void __launch_bounds__(256) adj_kernel(const float* __restrict__ adj,
                                                  float* __restrict__ out) {
    __shared__ int   scol[K];
    __shared__ short spos[K];
    __shared__ float buf[2][K];
    __shared__ int   ridx[ROWS_PER_CTA];

    const int b     = blockIdx.x >> 6;                 // 64 CTAs per batch
    const int rbase = (blockIdx.x & 63) * ROWS_PER_CTA;
    const int tid   = threadIdx.x;

#pragma unroll
    for (int q = 0; q < 4; q++) {
        int j = tid + q * 256;
        scol[j] = g_scol[b * K + j];
        spos[j] = (short)g_spos[b * K + j];
    }
    if (tid < ROWS_PER_CTA) ridx[tid] = g_topk_idx[b * K + rbase + tid];
    __syncthreads();

    const int c0 = scol[4 * tid],     c1 = scol[4 * tid + 1];
    const int c2 = scol[4 * tid + 2], c3 = scol[4 * tid + 3];
    const int p0 = spos[4 * tid],     p1 = spos[4 * tid + 1];
    const int p2 = spos[4 * tid + 2], p3 = spos[4 * tid + 3];

    const float* row0 = adj + ((size_t)b * N + ridx[0]) * N;
    float a0 = __ldg(row0 + c0), a1 = __ldg(row0 + c1);
    float a2 = __ldg(row0 + c2), a3 = __ldg(row0 + c3);

#pragma unroll
    for (int rr = 0; rr < ROWS_PER_CTA; rr++) {
        float n0, n1, n2, n3;
        if (rr + 1 < ROWS_PER_CTA) {
            const float* nr = adj + ((size_t)b * N + ridx[rr + 1]) * N;
            n0 = __ldg(nr + c0); n1 = __ldg(nr + c1);
            n2 = __ldg(nr + c2); n3 = __ldg(nr + c3);
        }
        float* bb = buf[rr & 1];
        bb[p0] = a0; bb[p1] = a1; bb[p2] = a2; bb[p3] = a3;
        __syncthreads();
        float4 w = *reinterpret_cast<float4*>(&bb[4 * tid]);
        float* orow = out + ((size_t)b * K + rbase + rr) * K;
        *reinterpret_cast<float4*>(orow + 4 * tid) = w;
        a0 = n0; a1 = n1; a2 = n2; a3 = n3;
        // buf[rr&1] re-scattered only at rr+2, after rr+1's barrier: safe.
    }
}

// ---------------------------------------------------------------------------
extern "C" void kernel_launch(void* const* d_in, const int* in_sizes, int n_in,
                              void* d_out, int out_size) {
    const float* ne  = (const float*)d_in[0];  // [B,N,F]
    const float* adj = (const float*)d_in[1];  // [B,N,N]
    const float* w   = (const float*)d_in[2];  // [F]
    float* out       = (float*)d_out;

    zero_hist_kernel<<<(B * NB + 1023) / 1024, 1024>>>();
    scores_kernel<<<(B * N) / 8, 256>>>(ne, w);
    topk_kernel<<<B, 1024>>>();
    nodes_kernel<<<(B * K) / 8, 256>>>(ne, out);
    adj_kernel<<<(B * K) / ROWS_PER_CTA, 256>>>(adj, out + (size_t)B * K * F);
}

// round 6
// speedup vs baseline: 1.1047x; 1.1047x over previous
#include <cuda_runtime.h>
#include <stdint.h>

#define B 16
#define N 4096
#define F 128
#define K 1024
#define ROWS_PER_CTA 8
#define ADJ_BLOCKS ((B * K) / ROWS_PER_CTA)   // 2048
#define HB 11
#define NB (1 << HB)   // 2048 histogram buckets

typedef unsigned long long u64;
typedef unsigned int u32;

// scratch (no allocations allowed)
__device__ float g_scores[B * N];
__device__ int   g_topk_idx[B * K];
__device__ float g_topk_val[B * K];
__device__ int   g_scol[B * K];   // selected columns sorted ascending
__device__ int   g_spos[B * K];   // original top-k position of that column

__device__ __forceinline__ unsigned map_f32(float f) {
    unsigned u = __float_as_uint(f);
    return (u & 0x80000000u) ? ~u : (u | 0x80000000u);
}

// ---------------------------------------------------------------------------
// Kernel 1: scores[b,n] = dot(node_embed[b,n,:], weight_p)  (one warp per row)
// ---------------------------------------------------------------------------
__global__ void scores_kernel(const float* __restrict__ ne,
                              const float* __restrict__ w) {
    int warp = (blockIdx.x * blockDim.x + threadIdx.x) >> 5;
    int lane = threadIdx.x & 31;
    if (warp >= B * N) return;
    const float4* nrow = reinterpret_cast<const float4*>(ne + (size_t)warp * F);
    const float4* wv   = reinterpret_cast<const float4*>(w);
    float4 a  = nrow[lane];
    float4 b4 = wv[lane];
    float s = a.x * b4.x + a.y * b4.y + a.z * b4.z + a.w * b4.w;
#pragma unroll
    for (int off = 16; off; off >>= 1)
        s += __shfl_xor_sync(0xffffffffu, s, off);
    if (lane == 0) g_scores[warp] = s;
}

// ---------------------------------------------------------------------------
// Kernel 2: radix-select + hybrid register/smem bitonic sort.
// key = (monotonic(score) << 12) | (4095 - idx) -> desc sort == jax top_k order
// ---------------------------------------------------------------------------
__device__ __forceinline__ u64 u64max(u64 a, u64 b) { return a > b ? a : b; }
__device__ __forceinline__ u64 u64min(u64 a, u64 b) { return a < b ? a : b; }

__device__ __forceinline__ void reg_stages(u64& e0, u64& e1, int i0, int i1,
                                           int lane, int kk) {
    if (kk >= 64) {
        bool desc = ((i0 & kk) == 0);
        if (desc ? (e0 < e1) : (e0 > e1)) { u64 t = e0; e0 = e1; e1 = t; }
    }
#pragma unroll
    for (int j = 16; j >= 1; j >>= 1) {
        if (j <= (kk >> 1)) {
            bool d0 = ((i0 & kk) == 0);
            bool d1 = ((i1 & kk) == 0);
            bool up = (lane & j) != 0;
            u64 p0 = __shfl_xor_sync(0xffffffffu, e0, j);
            u64 p1 = __shfl_xor_sync(0xffffffffu, e1, j);
            e0 = (d0 ^ up) ? u64max(e0, p0) : u64min(e0, p0);
            e1 = (d1 ^ up) ? u64max(e1, p1) : u64min(e1, p1);
        }
    }
}

__global__ void __launch_bounds__(1024) topk_kernel() {
    __shared__ u64 cand[4096];       // 32 KB
    __shared__ int hist[NB];         //  8 KB (reused as bitmap later)
    __shared__ int wsum[32];
    __shared__ int s_t0, s_cnt;

    const int b    = blockIdx.x;
    const int tid  = threadIdx.x;
    const int lane = tid & 31;
    const int warp = tid >> 5;
    const float* sc = g_scores + b * N;

    hist[tid] = 0;
    hist[tid + 1024] = 0;
    __syncthreads();

    u64 kreg[4];
#pragma unroll
    for (int q = 0; q < 4; q++) {
        int i = tid + q * 1024;
        unsigned m = map_f32(sc[i]);
        kreg[q] = (((u64)m) << 12) | (unsigned)(N - 1 - i);
        atomicAdd(&hist[m >> (32 - HB)], 1);
    }
    __syncthreads();

    // ---- cutoff bucket t0 = max t such that count(bucket >= t) >= K ----
    {
        int p = hist[2 * tid] + hist[2 * tid + 1];
        int ws = p;
#pragma unroll
        for (int off = 16; off; off >>= 1)
            ws += __shfl_xor_sync(0xffffffffu, ws, off);
        if (lane == 0) wsum[warp] = ws;
    }
    __syncthreads();
    if (warp == 0) {
        int v = wsum[lane];
        int s = v;
#pragma unroll
        for (int off = 1; off < 32; off <<= 1) {
            int t = __shfl_down_sync(0xffffffffu, s, off);
            if (lane + off < 32) s += t;
        }
        unsigned mm = __ballot_sync(0xffffffffu, s >= K);
        int wstar = 31 - __clz(mm);
        int sW = __shfl_sync(0xffffffffu, s, wstar);
        int vW = __shfl_sync(0xffffffffu, v, wstar);
        int run = sW - vW;
        int segbase = wstar * 64;
        int t0 = 0;
#pragma unroll
        for (int c = 1; c >= 0; c--) {
            int bkt = segbase + c * 32 + lane;
            int hv = hist[bkt];
            int s2 = hv;
#pragma unroll
            for (int off = 1; off < 32; off <<= 1) {
                int t = __shfl_down_sync(0xffffffffu, s2, off);
                if (lane + off < 32) s2 += t;
            }
            unsigned m2 = __ballot_sync(0xffffffffu, run + s2 >= K);
            if (m2) { t0 = segbase + c * 32 + (31 - __clz(m2)); break; }
            run += __shfl_sync(0xffffffffu, s2, 0);
        }
        if (lane == 0) { s_t0 = t0; s_cnt = 0; }
    }
    __syncthreads();

    // ---- compact candidates (bucket >= t0), warp-aggregated atomics ----
    int t0 = s_t0;
#pragma unroll
    for (int q = 0; q < 4; q++) {
        bool p = (int)(kreg[q] >> 33) >= t0;
        unsigned mask = __ballot_sync(0xffffffffu, p);
        int cnt = __popc(mask);
        int base = 0;
        if (lane == 0 && cnt) base = atomicAdd(&s_cnt, cnt);
        base = __shfl_sync(0xffffffffu, base, 0);
        if (p) cand[base + __popc(mask & ((1u << lane) - 1u))] = kreg[q];
    }
    __syncthreads();
    int M = s_cnt;

    if (M <= 2048) {
        for (int i = M + tid; i < 2048; i += 1024) cand[i] = 0;
        __syncthreads();

        const int base = warp * 64;
        const int i0 = base + lane, i1 = base + 32 + lane;
        u64 e0, e1;

        e0 = cand[i0]; e1 = cand[i1];
#pragma unroll
        for (int kk = 2; kk <= 64; kk <<= 1)
            reg_stages(e0, e1, i0, i1, lane, kk);
        cand[i0] = e0; cand[i1] = e1;
        __syncthreads();

#pragma unroll
        for (int kk = 128; kk <= 2048; kk <<= 1) {
            for (int j = kk >> 1; j >= 64; j >>= 1) {
                int i = 2 * tid - (tid & (j - 1));
                int x = i + j;
                bool desc = ((i & kk) == 0);
                u64 a = cand[i], c = cand[x];
                if (desc ? (a < c) : (a > c)) { cand[i] = c; cand[x] = a; }
                __syncthreads();
            }
            e0 = cand[i0]; e1 = cand[i1];
            reg_stages(e0, e1, i0, i1, lane, kk);
            cand[i0] = e0; cand[i1] = e1;
            __syncthreads();
        }
    } else {
        // safety fallback: plain full bitonic over all 4096 keys
#pragma unroll
        for (int q = 0; q < 4; q++) cand[tid + q * 1024] = kreg[q];
        __syncthreads();
        for (int kk = 2; kk <= 4096; kk <<= 1) {
            for (int j = kk >> 1; j > 0; j >>= 1) {
                for (int q = tid; q < 2048; q += 1024) {
                    int i = 2 * q - (q & (j - 1));
                    int x = i + j;
                    bool desc = ((i & kk) == 0);
                    u64 a = cand[i], c = cand[x];
                    if (desc ? (a < c) : (a > c)) { cand[i] = c; cand[x] = a; }
                }
                __syncthreads();
            }
        }
    }

    // ---- emit top-K (sorted desc) ----
    u64 key = cand[tid];
    int idx = (N - 1) - (int)(key & 0xFFFu);
    unsigned m = (unsigned)(key >> 12);
    unsigned u = (m & 0x80000000u) ? (m ^ 0x80000000u) : ~m;
    g_topk_idx[b * K + tid] = idx;
    g_topk_val[b * K + tid] = __uint_as_float(u);

    // ---- column-ascending permutation via bitmap counting-rank ----
    u32* bits = (u32*)hist;           // 4096-bit presence bitmap
    int* wordpref = hist + 128;
    if (tid < 128) bits[tid] = 0;
    __syncthreads();
    atomicOr(&bits[idx >> 5], 1u << (idx & 31));
    __syncthreads();
    if (warp == 0) {
        int s0 = __popc(bits[4 * lane]);
        int s1 = __popc(bits[4 * lane + 1]);
        int s2 = __popc(bits[4 * lane + 2]);
        int s3 = __popc(bits[4 * lane + 3]);
        int tot = s0 + s1 + s2 + s3;
        int ex = tot;
#pragma unroll
        for (int off = 1; off < 32; off <<= 1) {
            int t = __shfl_up_sync(0xffffffffu, ex, off);
            if (lane >= off) ex += t;
        }
        ex -= tot;
        wordpref[4 * lane]     = ex;
        wordpref[4 * lane + 1] = ex + s0;
        wordpref[4 * lane + 2] = ex + s0 + s1;
        wordpref[4 * lane + 3] = ex + s0 + s1 + s2;
    }
    __syncthreads();
    int wrd = idx >> 5, bit = idx & 31;
    int rank = wordpref[wrd] + __popc(bits[wrd] & ((1u << bit) - 1u));
    g_scol[b * K + rank] = idx;
    g_spos[b * K + rank] = tid;
}

// ---------------------------------------------------------------------------
// Kernel 3 (fused): blocks [0, ADJ_BLOCKS) do the adj gather;
// blocks [ADJ_BLOCKS, ADJ_BLOCKS + 2048) do pooled_nodes. Both depend only
// on topk and write disjoint output ranges, so they overlap on the chip.
// ---------------------------------------------------------------------------
__global__ void __launch_bounds__(256) fused_kernel(const float* __restrict__ ne,
                                                    const float* __restrict__ adj,
                                                    float* __restrict__ out) {
    if (blockIdx.x < ADJ_BLOCKS) {
        // ---------------- adj gather ----------------
        __shared__ int   scol[K];
        __shared__ short spos[K];
        __shared__ float buf[2][K];
        __shared__ int   ridx[ROWS_PER_CTA];

        float* aout = out + (size_t)B * K * F;
        const int b     = blockIdx.x >> 7;             // 128 CTAs per batch
        const int rbase = (blockIdx.x & 127) * ROWS_PER_CTA;
        const int tid   = threadIdx.x;

#pragma unroll
        for (int q = 0; q < 4; q++) {
            int j = tid + q * 256;
            scol[j] = g_scol[b * K + j];
            spos[j] = (short)g_spos[b * K + j];
        }
        if (tid < ROWS_PER_CTA) ridx[tid] = g_topk_idx[b * K + rbase + tid];
        __syncthreads();

        const int c0 = scol[4 * tid],     c1 = scol[4 * tid + 1];
        const int c2 = scol[4 * tid + 2], c3 = scol[4 * tid + 3];
        const int p0 = spos[4 * tid],     p1 = spos[4 * tid + 1];
        const int p2 = spos[4 * tid + 2], p3 = spos[4 * tid + 3];

        const float* row0 = adj + ((size_t)b * N + ridx[0]) * N;
        float a0 = __ldg(row0 + c0), a1 = __ldg(row0 + c1);
        float a2 = __ldg(row0 + c2), a3 = __ldg(row0 + c3);

#pragma unroll
        for (int rr = 0; rr < ROWS_PER_CTA; rr++) {
            float n0, n1, n2, n3;
            if (rr + 1 < ROWS_PER_CTA) {
                const float* nr = adj + ((size_t)b * N + ridx[rr + 1]) * N;
                n0 = __ldg(nr + c0); n1 = __ldg(nr + c1);
                n2 = __ldg(nr + c2); n3 = __ldg(nr + c3);
            }
            float* bb = buf[rr & 1];
            bb[p0] = a0; bb[p1] = a1; bb[p2] = a2; bb[p3] = a3;
            __syncthreads();
            float4 w = *reinterpret_cast<float4*>(&bb[4 * tid]);
            float* orow = aout + ((size_t)b * K + rbase + rr) * K;
            *reinterpret_cast<float4*>(orow + 4 * tid) = w;
            a0 = n0; a1 = n1; a2 = n2; a3 = n3;
        }
    } else {
        // ---------------- pooled_nodes ----------------
        int blk  = blockIdx.x - ADJ_BLOCKS;            // [0, 2048)
        int warp = (blk * 256 + (int)threadIdx.x) >> 5;  // [0, B*K)
        int lane = threadIdx.x & 31;
        int b    = warp >> 10;
        int idx  = g_topk_idx[warp];
        float g  = tanhf(g_topk_val[warp]);
        const float4* src = reinterpret_cast<const float4*>(
            ne + ((size_t)b * N + idx) * F);
        float4* dst = reinterpret_cast<float4*>(out + (size_t)warp * F);
        float4 v = src[lane];
        v.x *= g; v.y *= g; v.z *= g; v.w *= g;
        dst[lane] = v;
    }
}

// ---------------------------------------------------------------------------
extern "C" void kernel_launch(void* const* d_in, const int* in_sizes, int n_in,
                              void* d_out, int out_size) {
    const float* ne  = (const float*)d_in[0];  // [B,N,F]
    const float* adj = (const float*)d_in[1];  // [B,N,N]
    const float* w   = (const float*)d_in[2];  // [F]
    float* out       = (float*)d_out;

    scores_kernel<<<(B * N) / 8, 256>>>(ne, w);
    topk_kernel<<<B, 1024>>>();
    fused_kernel<<<ADJ_BLOCKS + (B * K) / 8, 256>>>(ne, adj, out);
}

// round 7
// speedup vs baseline: 1.1267x; 1.0199x over previous
#include <cuda_runtime.h>
#include <stdint.h>

#define B 16
#define N 4096
#define F 128
#define K 1024
#define ROWS_PER_CTA 8
#define ADJ_BLOCKS ((B * K) / ROWS_PER_CTA)   // 2048
#define HB 11
#define NB (1 << HB)   // 2048 histogram buckets

typedef unsigned long long u64;
typedef unsigned int u32;

// scratch (no allocations allowed)
__device__ float g_scores[B * N];
__device__ int   g_topk_idx[B * K];
__device__ float g_topk_val[B * K];
__device__ int   g_scol[B * K];   // selected columns sorted ascending
__device__ int   g_spos[B * K];   // original top-k position of that column

__device__ __forceinline__ unsigned map_f32(float f) {
    unsigned u = __float_as_uint(f);
    return (u & 0x80000000u) ? ~u : (u | 0x80000000u);
}

// ---------------------------------------------------------------------------
// Kernel 1: scores. 4 rows per warp -> 4 independent loads in flight per lane.
// ---------------------------------------------------------------------------
__global__ void scores_kernel(const float* __restrict__ ne,
                              const float* __restrict__ w) {
    int warp = (blockIdx.x * blockDim.x + threadIdx.x) >> 5;  // [0, B*N/4)
    int lane = threadIdx.x & 31;
    int row0 = warp * 4;
    if (row0 >= B * N) return;

    const float4* wv = reinterpret_cast<const float4*>(w);
    float4 b4 = wv[lane];
    const float4* r0 = reinterpret_cast<const float4*>(ne + (size_t)row0 * F);
    const float4* r1 = reinterpret_cast<const float4*>(ne + (size_t)(row0 + 1) * F);
    const float4* r2 = reinterpret_cast<const float4*>(ne + (size_t)(row0 + 2) * F);
    const float4* r3 = reinterpret_cast<const float4*>(ne + (size_t)(row0 + 3) * F);
    float4 a0 = r0[lane], a1 = r1[lane], a2 = r2[lane], a3 = r3[lane];

    float s0 = a0.x * b4.x + a0.y * b4.y + a0.z * b4.z + a0.w * b4.w;
    float s1 = a1.x * b4.x + a1.y * b4.y + a1.z * b4.z + a1.w * b4.w;
    float s2 = a2.x * b4.x + a2.y * b4.y + a2.z * b4.z + a2.w * b4.w;
    float s3 = a3.x * b4.x + a3.y * b4.y + a3.z * b4.z + a3.w * b4.w;
#pragma unroll
    for (int off = 16; off; off >>= 1) {
        s0 += __shfl_xor_sync(0xffffffffu, s0, off);
        s1 += __shfl_xor_sync(0xffffffffu, s1, off);
        s2 += __shfl_xor_sync(0xffffffffu, s2, off);
        s3 += __shfl_xor_sync(0xffffffffu, s3, off);
    }
    if (lane == 0)
        *reinterpret_cast<float4*>(g_scores + row0) = make_float4(s0, s1, s2, s3);
}

// ---------------------------------------------------------------------------
// Kernel 2: radix-select + hybrid register/smem bitonic sort.
// key = (monotonic(score) << 12) | (4095 - idx) -> desc sort == jax top_k order
// ---------------------------------------------------------------------------
__device__ __forceinline__ u64 u64max(u64 a, u64 b) { return a > b ? a : b; }
__device__ __forceinline__ u64 u64min(u64 a, u64 b) { return a < b ? a : b; }

__device__ __forceinline__ void reg_stages(u64& e0, u64& e1, int i0, int i1,
                                           int lane, int kk) {
    if (kk >= 64) {
        bool desc = ((i0 & kk) == 0);
        if (desc ? (e0 < e1) : (e0 > e1)) { u64 t = e0; e0 = e1; e1 = t; }
    }
#pragma unroll
    for (int j = 16; j >= 1; j >>= 1) {
        if (j <= (kk >> 1)) {
            bool d0 = ((i0 & kk) == 0);
            bool d1 = ((i1 & kk) == 0);
            bool up = (lane & j) != 0;
            u64 p0 = __shfl_xor_sync(0xffffffffu, e0, j);
            u64 p1 = __shfl_xor_sync(0xffffffffu, e1, j);
            e0 = (d0 ^ up) ? u64max(e0, p0) : u64min(e0, p0);
            e1 = (d1 ^ up) ? u64max(e1, p1) : u64min(e1, p1);
        }
    }
}

__global__ void __launch_bounds__(1024) topk_kernel() {
    __shared__ u64 cand[4096];       // 32 KB
    __shared__ int hist[NB];         //  8 KB (reused as bitmap later)
    __shared__ int wsum[32];
    __shared__ int s_t0, s_cnt;

    const int b    = blockIdx.x;
    const int tid  = threadIdx.x;
    const int lane = tid & 31;
    const int warp = tid >> 5;
    const float* sc = g_scores + b * N;

    hist[tid] = 0;
    hist[tid + 1024] = 0;
    __syncthreads();

    u64 kreg[4];
#pragma unroll
    for (int q = 0; q < 4; q++) {
        int i = tid + q * 1024;
        unsigned m = map_f32(sc[i]);
        kreg[q] = (((u64)m) << 12) | (unsigned)(N - 1 - i);
        atomicAdd(&hist[m >> (32 - HB)], 1);
    }
    __syncthreads();

    // ---- cutoff bucket t0 = max t such that count(bucket >= t) >= K ----
    {
        int p = hist[2 * tid] + hist[2 * tid + 1];
        int ws = p;
#pragma unroll
        for (int off = 16; off; off >>= 1)
            ws += __shfl_xor_sync(0xffffffffu, ws, off);
        if (lane == 0) wsum[warp] = ws;
    }
    __syncthreads();
    if (warp == 0) {
        int v = wsum[lane];
        int s = v;
#pragma unroll
        for (int off = 1; off < 32; off <<= 1) {
            int t = __shfl_down_sync(0xffffffffu, s, off);
            if (lane + off < 32) s += t;
        }
        unsigned mm = __ballot_sync(0xffffffffu, s >= K);
        int wstar = 31 - __clz(mm);
        int sW = __shfl_sync(0xffffffffu, s, wstar);
        int vW = __shfl_sync(0xffffffffu, v, wstar);
        int run = sW - vW;
        int segbase = wstar * 64;
        int t0 = 0;
#pragma unroll
        for (int c = 1; c >= 0; c--) {
            int bkt = segbase + c * 32 + lane;
            int hv = hist[bkt];
            int s2 = hv;
#pragma unroll
            for (int off = 1; off < 32; off <<= 1) {
                int t = __shfl_down_sync(0xffffffffu, s2, off);
                if (lane + off < 32) s2 += t;
            }
            unsigned m2 = __ballot_sync(0xffffffffu, run + s2 >= K);
            if (m2) { t0 = segbase + c * 32 + (31 - __clz(m2)); break; }
            run += __shfl_sync(0xffffffffu, s2, 0);
        }
        if (lane == 0) { s_t0 = t0; s_cnt = 0; }
    }
    __syncthreads();

    // ---- compact candidates (bucket >= t0), warp-aggregated atomics ----
    int t0 = s_t0;
#pragma unroll
    for (int q = 0; q < 4; q++) {
        bool p = (int)(kreg[q] >> 33) >= t0;
        unsigned mask = __ballot_sync(0xffffffffu, p);
        int cnt = __popc(mask);
        int base = 0;
        if (lane == 0 && cnt) base = atomicAdd(&s_cnt, cnt);
        base = __shfl_sync(0xffffffffu, base, 0);
        if (p) cand[base + __popc(mask & ((1u << lane) - 1u))] = kreg[q];
    }
    __syncthreads();
    int M = s_cnt;

    if (M <= 2048) {
        for (int i = M + tid; i < 2048; i += 1024) cand[i] = 0;
        __syncthreads();

        const int base = warp * 64;
        const int i0 = base + lane, i1 = base + 32 + lane;
        u64 e0, e1;

        e0 = cand[i0]; e1 = cand[i1];
#pragma unroll
        for (int kk = 2; kk <= 64; kk <<= 1)
            reg_stages(e0, e1, i0, i1, lane, kk);
        cand[i0] = e0; cand[i1] = e1;
        __syncthreads();

#pragma unroll
        for (int kk = 128; kk <= 2048; kk <<= 1) {
            for (int j = kk >> 1; j >= 64; j >>= 1) {
                int i = 2 * tid - (tid & (j - 1));
                int x = i + j;
                bool desc = ((i & kk) == 0);
                u64 a = cand[i], c = cand[x];
                if (desc ? (a < c) : (a > c)) { cand[i] = c; cand[x] = a; }
                __syncthreads();
            }
            e0 = cand[i0]; e1 = cand[i1];
            reg_stages(e0, e1, i0, i1, lane, kk);
            cand[i0] = e0; cand[i1] = e1;
            __syncthreads();
        }
    } else {
        // safety fallback: plain full bitonic over all 4096 keys
#pragma unroll
        for (int q = 0; q < 4; q++) cand[tid + q * 1024] = kreg[q];
        __syncthreads();
        for (int kk = 2; kk <= 4096; kk <<= 1) {
            for (int j = kk >> 1; j > 0; j >>= 1) {
                for (int q = tid; q < 2048; q += 1024) {
                    int i = 2 * q - (q & (j - 1));
                    int x = i + j;
                    bool desc = ((i & kk) == 0);
                    u64 a = cand[i], c = cand[x];
                    if (desc ? (a < c) : (a > c)) { cand[i] = c; cand[x] = a; }
                }
                __syncthreads();
            }
        }
    }

    // ---- emit top-K (sorted desc) ----
    u64 key = cand[tid];
    int idx = (N - 1) - (int)(key & 0xFFFu);
    unsigned m = (unsigned)(key >> 12);
    unsigned u = (m & 0x80000000u) ? (m ^ 0x80000000u) : ~m;
    g_topk_idx[b * K + tid] = idx;
    g_topk_val[b * K + tid] = __uint_as_float(u);

    // ---- column-ascending permutation via bitmap counting-rank ----
    u32* bits = (u32*)hist;           // 4096-bit presence bitmap
    int* wordpref = hist + 128;
    if (tid < 128) bits[tid] = 0;
    __syncthreads();
    atomicOr(&bits[idx >> 5], 1u << (idx & 31));
    __syncthreads();
    if (warp == 0) {
        int s0 = __popc(bits[4 * lane]);
        int s1 = __popc(bits[4 * lane + 1]);
        int s2 = __popc(bits[4 * lane + 2]);
        int s3 = __popc(bits[4 * lane + 3]);
        int tot = s0 + s1 + s2 + s3;
        int ex = tot;
#pragma unroll
        for (int off = 1; off < 32; off <<= 1) {
            int t = __shfl_up_sync(0xffffffffu, ex, off);
            if (lane >= off) ex += t;
        }
        ex -= tot;
        wordpref[4 * lane]     = ex;
        wordpref[4 * lane + 1] = ex + s0;
        wordpref[4 * lane + 2] = ex + s0 + s1;
        wordpref[4 * lane + 3] = ex + s0 + s1 + s2;
    }
    __syncthreads();
    int wrd = idx >> 5, bit = idx & 31;
    int rank = wordpref[wrd] + __popc(bits[wrd] & ((1u << bit) - 1u));
    g_scol[b * K + rank] = idx;
    g_spos[b * K + rank] = tid;
}

// ---------------------------------------------------------------------------
// Kernel 3 (fused): blocks [0, ADJ_BLOCKS) adj gather (prefetch depth 2);
// blocks [ADJ_BLOCKS, ...) pooled_nodes. Disjoint outputs, overlap on chip.
// ---------------------------------------------------------------------------
__global__ void __launch_bounds__(256) fused_kernel(const float* __restrict__ ne,
                                                    const float* __restrict__ adj,
                                                    float* __restrict__ out) {
    if (blockIdx.x < ADJ_BLOCKS) {
        __shared__ int   scol[K];
        __shared__ short spos[K];
        __shared__ float buf[2][K];
        __shared__ int   ridx[ROWS_PER_CTA];

        float* aout = out + (size_t)B * K * F;
        const int b     = blockIdx.x >> 7;             // 128 CTAs per batch
        const int rbase = (blockIdx.x & 127) * ROWS_PER_CTA;
        const int tid   = threadIdx.x;

#pragma unroll
        for (int q = 0; q < 4; q++) {
            int j = tid + q * 256;
            scol[j] = g_scol[b * K + j];
            spos[j] = (short)g_spos[b * K + j];
        }
        if (tid < ROWS_PER_CTA) ridx[tid] = g_topk_idx[b * K + rbase + tid];
        __syncthreads();

        const int c0 = scol[4 * tid],     c1 = scol[4 * tid + 1];
        const int c2 = scol[4 * tid + 2], c3 = scol[4 * tid + 3];
        const int p0 = spos[4 * tid],     p1 = spos[4 * tid + 1];
        const int p2 = spos[4 * tid + 2], p3 = spos[4 * tid + 3];

        // prefetch rows 0 and 1 (depth-2 pipeline)
        const float* r0 = adj + ((size_t)b * N + ridx[0]) * N;
        float a0 = __ldg(r0 + c0), a1 = __ldg(r0 + c1);
        float a2 = __ldg(r0 + c2), a3 = __ldg(r0 + c3);
        const float* r1 = adj + ((size_t)b * N + ridx[1]) * N;
        float n0 = __ldg(r1 + c0), n1 = __ldg(r1 + c1);
        float n2 = __ldg(r1 + c2), n3 = __ldg(r1 + c3);

#pragma unroll
        for (int rr = 0; rr < ROWS_PER_CTA; rr++) {
            float m0, m1, m2, m3;
            if (rr + 2 < ROWS_PER_CTA) {
                const float* nr = adj + ((size_t)b * N + ridx[rr + 2]) * N;
                m0 = __ldg(nr + c0); m1 = __ldg(nr + c1);
                m2 = __ldg(nr + c2); m3 = __ldg(nr + c3);
            }
            float* bb = buf[rr & 1];
            bb[p0] = a0; bb[p1] = a1; bb[p2] = a2; bb[p3] = a3;
            __syncthreads();
            float4 w = *reinterpret_cast<float4*>(&bb[4 * tid]);
            float* orow = aout + ((size_t)b * K + rbase + rr) * K;
            *reinterpret_cast<float4*>(orow + 4 * tid) = w;
            a0 = n0; a1 = n1; a2 = n2; a3 = n3;
            n0 = m0; n1 = m1; n2 = m2; n3 = m3;
            // buf[rr&1] re-scattered at rr+2, after rr+1's barrier: safe.
        }
    } else {
        int blk  = blockIdx.x - ADJ_BLOCKS;              // [0, 2048)
        int warp = (blk * 256 + (int)threadIdx.x) >> 5;  // [0, B*K)
        int lane = threadIdx.x & 31;
        int b    = warp >> 10;
        int idx  = g_topk_idx[warp];
        float g  = tanhf(g_topk_val[warp]);
        const float4* src = reinterpret_cast<const float4*>(
            ne + ((size_t)b * N + idx) * F);
        float4* dst = reinterpret_cast<float4*>(out + (size_t)warp * F);
        float4 v = src[lane];
        v.x *= g; v.y *= g; v.z *= g; v.w *= g;
        dst[lane] = v;
    }
}

// ---------------------------------------------------------------------------
extern "C" void kernel_launch(void* const* d_in, const int* in_sizes, int n_in,
                              void* d_out, int out_size) {
    const float* ne  = (const float*)d_in[0];  // [B,N,F]
    const float* adj = (const float*)d_in[1];  // [B,N,N]
    const float* w   = (const float*)d_in[2];  // [F]
    float* out       = (float*)d_out;

    scores_kernel<<<(B * N) / 32, 256>>>(ne, w);   // 4 rows per warp
    topk_kernel<<<B, 1024>>>();
    fused_kernel<<<ADJ_BLOCKS + (B * K) / 8, 256>>>(ne, adj, out);
}